// round 6
// baseline (speedup 1.0000x reference)
#include <cuda_runtime.h>
#include <cstdint>

#define N_NODES 100000
#define N_EDGES 1600000
#define F 256          // IN_FEATS == H_FEATS
#define C 64           // NUM_CLASSES

// ---------------- scratch (static device globals; no allocation) -------------
__device__ int   g_deg_out[N_NODES];
__device__ int   g_deg_in[N_NODES];
__device__ float g_h[(size_t)N_NODES * F];      // (x * rsqrt(deg_out)) @ W
__device__ float g_pooled[F];                   // sum over nodes of relu(...)
__device__ int   g_is64;                        // 1 if src/dst are int64
// CSR-by-dst
__device__ int   g_row_ptr[N_NODES + 1];
__device__ int   g_cursor[N_NODES];
__device__ int   g_edge_src[N_EDGES];
#define SCAN_BLOCKS 1024
__device__ int   g_blocksum[SCAN_BLOCKS];
__device__ int   g_blockoff[SCAN_BLOCKS];

// ---------------- K-1: index dtype probe --------------------------------------
__global__ void detect_kernel(const unsigned int* __restrict__ words) {
    __shared__ int nonzero;
    if (threadIdx.x == 0) nonzero = 0;
    __syncthreads();
    for (int p = threadIdx.x; p < 1024; p += blockDim.x)
        if (words[2 * p + 1] != 0u) atomicOr(&nonzero, 1);
    __syncthreads();
    if (threadIdx.x == 0) g_is64 = (nonzero == 0) ? 1 : 0;
}

__device__ __forceinline__ int load_idx(const void* p, int i, int is64) {
    return is64 ? (int)((const long long*)p)[i] : ((const int*)p)[i];
}

// ---------------- K0: zero scratch -------------------------------------------
__global__ void zero_kernel(int nodes) {
    int tid    = blockIdx.x * blockDim.x + threadIdx.x;
    int stride = gridDim.x * blockDim.x;
    for (int i = tid; i < nodes; i += stride) {
        g_deg_out[i] = 0;
        g_deg_in[i]  = 0;
    }
    if (tid < F) g_pooled[tid] = 0.f;
}

// ---------------- K1: degree counts ------------------------------------------
__global__ void deg_kernel(const void* __restrict__ src,
                           const void* __restrict__ dst, int nE) {
    int i = blockIdx.x * blockDim.x + threadIdx.x;
    int is64 = g_is64;
    if (i < nE) {
        atomicAdd(&g_deg_out[load_idx(src, i, is64)], 1);
        atomicAdd(&g_deg_in[load_idx(dst, i, is64)], 1);
    }
}

// ---------------- CSR build: 3-phase block scan of deg_in --------------------
__global__ void scan_a_kernel(int nodes) {
    __shared__ int s[256];
    int i = blockIdx.x * 256 + threadIdx.x;
    s[threadIdx.x] = (i < nodes) ? g_deg_in[i] : 0;
    __syncthreads();
#pragma unroll
    for (int off = 128; off > 0; off >>= 1) {
        if (threadIdx.x < off) s[threadIdx.x] += s[threadIdx.x + off];
        __syncthreads();
    }
    if (threadIdx.x == 0) g_blocksum[blockIdx.x] = s[0];
}

__global__ void scan_b_kernel(int nblocks) {
    __shared__ int s[SCAN_BLOCKS];
    int t = threadIdx.x;
    s[t] = (t < nblocks) ? g_blocksum[t] : 0;
    __syncthreads();
#pragma unroll
    for (int off = 1; off < SCAN_BLOCKS; off <<= 1) {
        int v = (t >= off) ? s[t - off] : 0;
        __syncthreads();
        s[t] += v;
        __syncthreads();
    }
    if (t < nblocks) g_blockoff[t] = (t == 0) ? 0 : s[t - 1];
}

__global__ void scan_c_kernel(int nodes) {
    __shared__ int s[256];
    int i = blockIdx.x * 256 + threadIdx.x;
    int t = threadIdx.x;
    int d = (i < nodes) ? g_deg_in[i] : 0;
    s[t] = d;
    __syncthreads();
#pragma unroll
    for (int off = 1; off < 256; off <<= 1) {
        int v = (t >= off) ? s[t - off] : 0;
        __syncthreads();
        s[t] += v;
        __syncthreads();
    }
    int excl = g_blockoff[blockIdx.x] + s[t] - d;
    if (i < nodes) {
        g_row_ptr[i] = excl;
        g_cursor[i]  = excl;
        if (i == nodes - 1) g_row_ptr[nodes] = excl + d;
    }
}

__global__ void scatter_kernel(const void* __restrict__ src,
                               const void* __restrict__ dst, int nE) {
    int i = blockIdx.x * blockDim.x + threadIdx.x;
    int is64 = g_is64;
    if (i < nE) {
        int d = load_idx(dst, i, is64);
        int pos = atomicAdd(&g_cursor[d], 1);
        g_edge_src[pos] = load_idx(src, i, is64);
    }
}

// ---------------- K2: GEMM  h = (x * rsqrt(deg_out)) @ W ---------------------
// 128x128 block tile, BK=16, 256 threads (16x16), 8x8 register micro-tiles.
// Register-prefetch software pipeline over k-tiles. Row scale fused at output.
#define BM 128
#define BN 128
#define BK 16

__global__ __launch_bounds__(256) void gemm_kernel(const float* __restrict__ x,
                                                   const float* __restrict__ W,
                                                   int M) {
    __shared__ float As[BK][BM + 4];   // transposed A tile
    __shared__ float Bs[BK][BN];

    const int t  = threadIdx.x;
    const int bm = blockIdx.x * BM;
    const int bn = blockIdx.y * BN;
    const int tx = t & 15;             // 0..15 -> 8 cols
    const int ty = t >> 4;             // 0..15 -> 8 rows

    // A tile: 128 rows x 16 cols = 512 float4 -> 2 per thread
    const int aRow  = t >> 2;          // 0..63 (and +64)
    const int aCol4 = (t & 3) << 2;    // 0,4,8,12
    // B tile: 16 rows x 128 cols = 512 float4 -> 2 per thread
    const int bRow  = t >> 5;          // 0..7 (and +8)
    const int bCol4 = (t & 31) << 2;   // 0..124

    float acc[8][8] = {};
    float4 pa[2], pb[2];

    const int nTiles = F / BK;

    // prologue: load tile 0 into regs
    {
        const int k0 = 0;
#pragma unroll
        for (int half = 0; half < 2; half++) {
            int r = aRow + half * 64;
            pa[half] = make_float4(0.f, 0.f, 0.f, 0.f);
            if (bm + r < M)
                pa[half] = *reinterpret_cast<const float4*>(x + (size_t)(bm + r) * F + k0 + aCol4);
            pb[half] = *reinterpret_cast<const float4*>(W + (size_t)(k0 + bRow + half * 8) * F + bn + bCol4);
        }
    }

    for (int kt = 0; kt < nTiles; kt++) {
        // store prefetched regs to smem
#pragma unroll
        for (int half = 0; half < 2; half++) {
            int r = aRow + half * 64;
            As[aCol4 + 0][r] = pa[half].x;
            As[aCol4 + 1][r] = pa[half].y;
            As[aCol4 + 2][r] = pa[half].z;
            As[aCol4 + 3][r] = pa[half].w;
            *reinterpret_cast<float4*>(&Bs[bRow + half * 8][bCol4]) = pb[half];
        }
        __syncthreads();

        // prefetch next tile into regs (overlaps with compute below)
        if (kt + 1 < nTiles) {
            const int k0 = (kt + 1) * BK;
#pragma unroll
            for (int half = 0; half < 2; half++) {
                int r = aRow + half * 64;
                pa[half] = make_float4(0.f, 0.f, 0.f, 0.f);
                if (bm + r < M)
                    pa[half] = *reinterpret_cast<const float4*>(x + (size_t)(bm + r) * F + k0 + aCol4);
                pb[half] = *reinterpret_cast<const float4*>(W + (size_t)(k0 + bRow + half * 8) * F + bn + bCol4);
            }
        }

#pragma unroll
        for (int k = 0; k < BK; k++) {
            float4 ra0 = *reinterpret_cast<const float4*>(&As[k][ty << 3]);
            float4 ra1 = *reinterpret_cast<const float4*>(&As[k][(ty << 3) + 4]);
            float4 rb0 = *reinterpret_cast<const float4*>(&Bs[k][tx << 3]);
            float4 rb1 = *reinterpret_cast<const float4*>(&Bs[k][(tx << 3) + 4]);
            float a[8] = {ra0.x, ra0.y, ra0.z, ra0.w, ra1.x, ra1.y, ra1.z, ra1.w};
            float b[8] = {rb0.x, rb0.y, rb0.z, rb0.w, rb1.x, rb1.y, rb1.z, rb1.w};
#pragma unroll
            for (int i = 0; i < 8; i++)
#pragma unroll
                for (int j = 0; j < 8; j++) acc[i][j] = fmaf(a[i], b[j], acc[i][j]);
        }
        __syncthreads();
    }

#pragma unroll
    for (int i = 0; i < 8; i++) {
        int m = bm + (ty << 3) + i;
        if (m < M) {
            float s = rsqrtf((float)max(g_deg_out[m], 1));
            float4 o0 = make_float4(acc[i][0] * s, acc[i][1] * s, acc[i][2] * s, acc[i][3] * s);
            float4 o1 = make_float4(acc[i][4] * s, acc[i][5] * s, acc[i][6] * s, acc[i][7] * s);
            float* outp = g_h + (size_t)m * F + bn + (tx << 3);
            *reinterpret_cast<float4*>(outp)     = o0;
            *reinterpret_cast<float4*>(outp + 4) = o1;
        }
    }
}

// ---------------- K3: CSR aggregate + epilogue + pool -------------------------
__global__ __launch_bounds__(256) void agg_kernel(const float* __restrict__ b,
                                                  int nodes) {
    __shared__ float pooled_s[F];
    if (threadIdx.x < F) pooled_s[threadIdx.x] = 0.f;
    __syncthreads();

    int warp = (blockIdx.x * blockDim.x + threadIdx.x) >> 5;
    int lane = threadIdx.x & 31;

    if (warp < nodes) {
        int begin = g_row_ptr[warp];
        int end   = g_row_ptr[warp + 1];

        float4 a0 = make_float4(0.f, 0.f, 0.f, 0.f);
        float4 a1 = make_float4(0.f, 0.f, 0.f, 0.f);

        int e = begin;
        for (; e + 1 < end; e += 2) {
            int s0 = g_edge_src[e];
            int s1 = g_edge_src[e + 1];
            const float4* r0 = reinterpret_cast<const float4*>(g_h + (size_t)s0 * F);
            const float4* r1 = reinterpret_cast<const float4*>(g_h + (size_t)s1 * F);
            float4 v00 = r0[lane], v01 = r0[lane + 32];
            float4 v10 = r1[lane], v11 = r1[lane + 32];
            a0.x += v00.x + v10.x; a0.y += v00.y + v10.y;
            a0.z += v00.z + v10.z; a0.w += v00.w + v10.w;
            a1.x += v01.x + v11.x; a1.y += v01.y + v11.y;
            a1.z += v01.z + v11.z; a1.w += v01.w + v11.w;
        }
        if (e < end) {
            int s0 = g_edge_src[e];
            const float4* r0 = reinterpret_cast<const float4*>(g_h + (size_t)s0 * F);
            float4 v00 = r0[lane], v01 = r0[lane + 32];
            a0.x += v00.x; a0.y += v00.y; a0.z += v00.z; a0.w += v00.w;
            a1.x += v01.x; a1.y += v01.y; a1.z += v01.z; a1.w += v01.w;
        }

        float rs = rsqrtf((float)max(end - begin, 1));
        const float4* b4 = reinterpret_cast<const float4*>(b);
        float4 b0 = b4[lane], b1 = b4[lane + 32];

        float4 o0, o1;
        o0.x = fmaxf(fmaf(a0.x, rs, b0.x), 0.f);
        o0.y = fmaxf(fmaf(a0.y, rs, b0.y), 0.f);
        o0.z = fmaxf(fmaf(a0.z, rs, b0.z), 0.f);
        o0.w = fmaxf(fmaf(a0.w, rs, b0.w), 0.f);
        o1.x = fmaxf(fmaf(a1.x, rs, b1.x), 0.f);
        o1.y = fmaxf(fmaf(a1.y, rs, b1.y), 0.f);
        o1.z = fmaxf(fmaf(a1.z, rs, b1.z), 0.f);
        o1.w = fmaxf(fmaf(a1.w, rs, b1.w), 0.f);

        int f0 = lane << 2;
        atomicAdd(&pooled_s[f0 + 0], o0.x);
        atomicAdd(&pooled_s[f0 + 1], o0.y);
        atomicAdd(&pooled_s[f0 + 2], o0.z);
        atomicAdd(&pooled_s[f0 + 3], o0.w);
        int f1 = (lane + 32) << 2;
        atomicAdd(&pooled_s[f1 + 0], o1.x);
        atomicAdd(&pooled_s[f1 + 1], o1.y);
        atomicAdd(&pooled_s[f1 + 2], o1.z);
        atomicAdd(&pooled_s[f1 + 3], o1.w);
    }

    __syncthreads();
    if (threadIdx.x < F) atomicAdd(&g_pooled[threadIdx.x], pooled_s[threadIdx.x]);
}

// ---------------- K5: head  softmax(pooled/N @ W2 + b2) ----------------------
__global__ __launch_bounds__(64) void head_kernel(const float* __restrict__ W2,
                                                  const float* __restrict__ b2,
                                                  float* __restrict__ out, float invN) {
    __shared__ float pooled_s[F];
    __shared__ float sm[C];
    int t = threadIdx.x;
    for (int j = t; j < F; j += C) pooled_s[j] = g_pooled[j] * invN;
    __syncthreads();

    float acc = b2[t];
#pragma unroll 8
    for (int j = 0; j < F; j++) acc = fmaf(pooled_s[j], W2[(size_t)j * C + t], acc);

    sm[t] = acc;
    __syncthreads();
    float m = sm[0];
#pragma unroll
    for (int j = 1; j < C; j++) m = fmaxf(m, sm[j]);
    __syncthreads();
    float e = expf(acc - m);
    sm[t] = e;
    __syncthreads();
    float ssum = 0.f;
#pragma unroll
    for (int j = 0; j < C; j++) ssum += sm[j];
    out[t] = e / ssum;
}

// ---------------- launch ------------------------------------------------------
extern "C" void kernel_launch(void* const* d_in, const int* in_sizes, int n_in,
                              void* d_out, int out_size) {
    const float* x   = (const float*)d_in[0];
    const void*  src = d_in[1];
    const void*  dst = d_in[2];
    const float* W   = (const float*)d_in[3];
    const float* b   = (const float*)d_in[4];
    const float* W2  = (const float*)d_in[5];
    const float* b2  = (const float*)d_in[6];
    float*       out = (float*)d_out;

    const int nodes = in_sizes[0] / F;     // 100000
    const int nE    = in_sizes[1];         // 1600000
    const int nScanBlocks = (nodes + 255) / 256;

    detect_kernel<<<1, 256>>>((const unsigned int*)src);
    zero_kernel<<<256, 256>>>(nodes);
    deg_kernel<<<(nE + 255) / 256, 256>>>(src, dst, nE);

    // CSR build
    scan_a_kernel<<<nScanBlocks, 256>>>(nodes);
    scan_b_kernel<<<1, SCAN_BLOCKS>>>(nScanBlocks);
    scan_c_kernel<<<nScanBlocks, 256>>>(nodes);
    scatter_kernel<<<(nE + 255) / 256, 256>>>(src, dst, nE);

    // GEMM (fused rsqrt(out_deg) row scale)
    dim3 ggrid((nodes + BM - 1) / BM, F / BN);
    gemm_kernel<<<ggrid, 256>>>(x, W, nodes);

    // CSR aggregate + epilogue + pool
    int ablocks = (nodes + 7) / 8;
    agg_kernel<<<ablocks, 256>>>(b, nodes);

    head_kernel<<<1, C>>>(W2, b2, out, 1.0f / (float)nodes);
}

// round 8
// speedup vs baseline: 1.1194x; 1.1194x over previous
#include <cuda_runtime.h>
#include <cstdint>

#define N_NODES 100000
#define N_EDGES 1600000
#define F 256          // IN_FEATS == H_FEATS
#define C 64           // NUM_CLASSES

// ---------------- scratch (static device globals; no allocation) -------------
__device__ int   g_deg_out[N_NODES];
__device__ int   g_deg_in[N_NODES];
__device__ float g_rs_out[N_NODES];             // rsqrt(max(deg_out,1))
__device__ float g_h[(size_t)N_NODES * F];      // x @ W  (unscaled)
__device__ float g_pooled[F];                   // sum over nodes of relu(...)
__device__ int   g_is64;                        // 1 if src/dst are int64
// CSR-by-dst
__device__ int   g_row_ptr[N_NODES + 1];
__device__ int   g_cursor[N_NODES];
__device__ int   g_edge_src[N_EDGES];
#define SCAN_BLOCKS 1024
__device__ int   g_blocksum[SCAN_BLOCKS];
__device__ int   g_blockoff[SCAN_BLOCKS];

// ---------------- K-1: index dtype probe --------------------------------------
__global__ void detect_kernel(const unsigned int* __restrict__ words) {
    __shared__ int nonzero;
    if (threadIdx.x == 0) nonzero = 0;
    __syncthreads();
    for (int p = threadIdx.x; p < 1024; p += blockDim.x)
        if (words[2 * p + 1] != 0u) atomicOr(&nonzero, 1);
    __syncthreads();
    if (threadIdx.x == 0) g_is64 = (nonzero == 0) ? 1 : 0;
}

__device__ __forceinline__ int load_idx(const void* p, int i, int is64) {
    return is64 ? (int)((const long long*)p)[i] : ((const int*)p)[i];
}

// ---------------- K0: zero scratch -------------------------------------------
__global__ void zero_kernel(int nodes) {
    int tid    = blockIdx.x * blockDim.x + threadIdx.x;
    int stride = gridDim.x * blockDim.x;
    for (int i = tid; i < nodes; i += stride) {
        g_deg_out[i] = 0;
        g_deg_in[i]  = 0;
    }
    if (tid < F) g_pooled[tid] = 0.f;
}

// ---------------- K1: degree counts ------------------------------------------
__global__ void deg_kernel(const void* __restrict__ src,
                           const void* __restrict__ dst, int nE) {
    int i = blockIdx.x * blockDim.x + threadIdx.x;
    int is64 = g_is64;
    if (i < nE) {
        atomicAdd(&g_deg_out[load_idx(src, i, is64)], 1);
        atomicAdd(&g_deg_in[load_idx(dst, i, is64)], 1);
    }
}

// ---------------- K1b: rsqrt(out_deg) precompute -------------------------------
__global__ void rs_kernel(int nodes) {
    int i = blockIdx.x * blockDim.x + threadIdx.x;
    if (i < nodes) g_rs_out[i] = rsqrtf((float)max(g_deg_out[i], 1));
}

// ---------------- CSR build: 3-phase block scan of deg_in --------------------
__global__ void scan_a_kernel(int nodes) {
    __shared__ int s[256];
    int i = blockIdx.x * 256 + threadIdx.x;
    s[threadIdx.x] = (i < nodes) ? g_deg_in[i] : 0;
    __syncthreads();
#pragma unroll
    for (int off = 128; off > 0; off >>= 1) {
        if (threadIdx.x < off) s[threadIdx.x] += s[threadIdx.x + off];
        __syncthreads();
    }
    if (threadIdx.x == 0) g_blocksum[blockIdx.x] = s[0];
}

__global__ void scan_b_kernel(int nblocks) {
    __shared__ int s[SCAN_BLOCKS];
    int t = threadIdx.x;
    s[t] = (t < nblocks) ? g_blocksum[t] : 0;
    __syncthreads();
#pragma unroll
    for (int off = 1; off < SCAN_BLOCKS; off <<= 1) {
        int v = (t >= off) ? s[t - off] : 0;
        __syncthreads();
        s[t] += v;
        __syncthreads();
    }
    if (t < nblocks) g_blockoff[t] = (t == 0) ? 0 : s[t - 1];
}

__global__ void scan_c_kernel(int nodes) {
    __shared__ int s[256];
    int i = blockIdx.x * 256 + threadIdx.x;
    int t = threadIdx.x;
    int d = (i < nodes) ? g_deg_in[i] : 0;
    s[t] = d;
    __syncthreads();
#pragma unroll
    for (int off = 1; off < 256; off <<= 1) {
        int v = (t >= off) ? s[t - off] : 0;
        __syncthreads();
        s[t] += v;
        __syncthreads();
    }
    int excl = g_blockoff[blockIdx.x] + s[t] - d;
    if (i < nodes) {
        g_row_ptr[i] = excl;
        g_cursor[i]  = excl;
        if (i == nodes - 1) g_row_ptr[nodes] = excl + d;
    }
}

__global__ void scatter_kernel(const void* __restrict__ src,
                               const void* __restrict__ dst, int nE) {
    int i = blockIdx.x * blockDim.x + threadIdx.x;
    int is64 = g_is64;
    if (i < nE) {
        int d = load_idx(dst, i, is64);
        int pos = atomicAdd(&g_cursor[d], 1);
        g_edge_src[pos] = load_idx(src, i, is64);
    }
}

// ---------------- K2: GEMM  h = x @ W  (no scale; reverted R4 config) --------
#define BM 128
#define BN 64
#define BK 16

__global__ __launch_bounds__(256) void gemm_kernel(const float* __restrict__ x,
                                                   const float* __restrict__ W,
                                                   int M) {
    __shared__ float As[BK][BM + 4];
    __shared__ float Bs[BK][BN];

    const int t  = threadIdx.x;
    const int bm = blockIdx.x * BM;
    const int bn = blockIdx.y * BN;
    const int tx = t & 15;
    const int ty = t >> 4;

    const int aRow  = t >> 2;
    const int aCol4 = (t & 3) << 2;
    const int bRow  = t >> 4;
    const int bCol4 = (t & 15) << 2;

    float acc[8][4] = {};

    for (int k0 = 0; k0 < F; k0 += BK) {
#pragma unroll
        for (int half = 0; half < 2; half++) {
            int r = aRow + half * 64;
            float4 av = make_float4(0.f, 0.f, 0.f, 0.f);
            if (bm + r < M)
                av = *reinterpret_cast<const float4*>(x + (size_t)(bm + r) * F + k0 + aCol4);
            As[aCol4 + 0][r] = av.x;
            As[aCol4 + 1][r] = av.y;
            As[aCol4 + 2][r] = av.z;
            As[aCol4 + 3][r] = av.w;
        }
        float4 bv = *reinterpret_cast<const float4*>(W + (size_t)(k0 + bRow) * F + bn + bCol4);
        *reinterpret_cast<float4*>(&Bs[bRow][bCol4]) = bv;

        __syncthreads();

#pragma unroll
        for (int k = 0; k < BK; k++) {
            float4 ra0 = *reinterpret_cast<const float4*>(&As[k][ty << 3]);
            float4 ra1 = *reinterpret_cast<const float4*>(&As[k][(ty << 3) + 4]);
            float4 rb  = *reinterpret_cast<const float4*>(&Bs[k][tx << 2]);
            float a[8] = {ra0.x, ra0.y, ra0.z, ra0.w, ra1.x, ra1.y, ra1.z, ra1.w};
            float b[4] = {rb.x, rb.y, rb.z, rb.w};
#pragma unroll
            for (int i = 0; i < 8; i++)
#pragma unroll
                for (int j = 0; j < 4; j++) acc[i][j] = fmaf(a[i], b[j], acc[i][j]);
        }
        __syncthreads();
    }

#pragma unroll
    for (int i = 0; i < 8; i++) {
        int m = bm + (ty << 3) + i;
        if (m < M) {
            float4 o = make_float4(acc[i][0], acc[i][1], acc[i][2], acc[i][3]);
            *reinterpret_cast<float4*>(g_h + (size_t)m * F + bn + (tx << 2)) = o;
        }
    }
}

// ---------------- K3: CSR aggregate + epilogue + pool -------------------------
// One warp per dst node. Source-side scale rs_out[s] applied per edge (FMA).
__global__ __launch_bounds__(256) void agg_kernel(const float* __restrict__ b,
                                                  int nodes) {
    __shared__ float pooled_s[F];
    if (threadIdx.x < F) pooled_s[threadIdx.x] = 0.f;
    __syncthreads();

    int warp = (blockIdx.x * blockDim.x + threadIdx.x) >> 5;
    int lane = threadIdx.x & 31;

    if (warp < nodes) {
        int begin = g_row_ptr[warp];
        int end   = g_row_ptr[warp + 1];

        float4 a0 = make_float4(0.f, 0.f, 0.f, 0.f);
        float4 a1 = make_float4(0.f, 0.f, 0.f, 0.f);

        int e = begin;
        for (; e + 1 < end; e += 2) {
            int s0 = g_edge_src[e];
            int s1 = g_edge_src[e + 1];
            float w0 = g_rs_out[s0];
            float w1 = g_rs_out[s1];
            const float4* r0 = reinterpret_cast<const float4*>(g_h + (size_t)s0 * F);
            const float4* r1 = reinterpret_cast<const float4*>(g_h + (size_t)s1 * F);
            float4 v00 = r0[lane], v01 = r0[lane + 32];
            float4 v10 = r1[lane], v11 = r1[lane + 32];
            a0.x = fmaf(v00.x, w0, a0.x); a0.y = fmaf(v00.y, w0, a0.y);
            a0.z = fmaf(v00.z, w0, a0.z); a0.w = fmaf(v00.w, w0, a0.w);
            a1.x = fmaf(v01.x, w0, a1.x); a1.y = fmaf(v01.y, w0, a1.y);
            a1.z = fmaf(v01.z, w0, a1.z); a1.w = fmaf(v01.w, w0, a1.w);
            a0.x = fmaf(v10.x, w1, a0.x); a0.y = fmaf(v10.y, w1, a0.y);
            a0.z = fmaf(v10.z, w1, a0.z); a0.w = fmaf(v10.w, w1, a0.w);
            a1.x = fmaf(v11.x, w1, a1.x); a1.y = fmaf(v11.y, w1, a1.y);
            a1.z = fmaf(v11.z, w1, a1.z); a1.w = fmaf(v11.w, w1, a1.w);
        }
        if (e < end) {
            int s0 = g_edge_src[e];
            float w0 = g_rs_out[s0];
            const float4* r0 = reinterpret_cast<const float4*>(g_h + (size_t)s0 * F);
            float4 v00 = r0[lane], v01 = r0[lane + 32];
            a0.x = fmaf(v00.x, w0, a0.x); a0.y = fmaf(v00.y, w0, a0.y);
            a0.z = fmaf(v00.z, w0, a0.z); a0.w = fmaf(v00.w, w0, a0.w);
            a1.x = fmaf(v01.x, w0, a1.x); a1.y = fmaf(v01.y, w0, a1.y);
            a1.z = fmaf(v01.z, w0, a1.z); a1.w = fmaf(v01.w, w0, a1.w);
        }

        float rs = rsqrtf((float)max(end - begin, 1));
        const float4* b4 = reinterpret_cast<const float4*>(b);
        float4 b0 = b4[lane], b1 = b4[lane + 32];

        float4 o0, o1;
        o0.x = fmaxf(fmaf(a0.x, rs, b0.x), 0.f);
        o0.y = fmaxf(fmaf(a0.y, rs, b0.y), 0.f);
        o0.z = fmaxf(fmaf(a0.z, rs, b0.z), 0.f);
        o0.w = fmaxf(fmaf(a0.w, rs, b0.w), 0.f);
        o1.x = fmaxf(fmaf(a1.x, rs, b1.x), 0.f);
        o1.y = fmaxf(fmaf(a1.y, rs, b1.y), 0.f);
        o1.z = fmaxf(fmaf(a1.z, rs, b1.z), 0.f);
        o1.w = fmaxf(fmaf(a1.w, rs, b1.w), 0.f);

        int f0 = lane << 2;
        atomicAdd(&pooled_s[f0 + 0], o0.x);
        atomicAdd(&pooled_s[f0 + 1], o0.y);
        atomicAdd(&pooled_s[f0 + 2], o0.z);
        atomicAdd(&pooled_s[f0 + 3], o0.w);
        int f1 = (lane + 32) << 2;
        atomicAdd(&pooled_s[f1 + 0], o1.x);
        atomicAdd(&pooled_s[f1 + 1], o1.y);
        atomicAdd(&pooled_s[f1 + 2], o1.z);
        atomicAdd(&pooled_s[f1 + 3], o1.w);
    }

    __syncthreads();
    if (threadIdx.x < F) atomicAdd(&g_pooled[threadIdx.x], pooled_s[threadIdx.x]);
}

// ---------------- K5: head  softmax(pooled/N @ W2 + b2) ----------------------
__global__ __launch_bounds__(64) void head_kernel(const float* __restrict__ W2,
                                                  const float* __restrict__ b2,
                                                  float* __restrict__ out, float invN) {
    __shared__ float pooled_s[F];
    __shared__ float sm[C];
    int t = threadIdx.x;
    for (int j = t; j < F; j += C) pooled_s[j] = g_pooled[j] * invN;
    __syncthreads();

    float acc = b2[t];
#pragma unroll 8
    for (int j = 0; j < F; j++) acc = fmaf(pooled_s[j], W2[(size_t)j * C + t], acc);

    sm[t] = acc;
    __syncthreads();
    float m = sm[0];
#pragma unroll
    for (int j = 1; j < C; j++) m = fmaxf(m, sm[j]);
    __syncthreads();
    float e = expf(acc - m);
    sm[t] = e;
    __syncthreads();
    float ssum = 0.f;
#pragma unroll
    for (int j = 0; j < C; j++) ssum += sm[j];
    out[t] = e / ssum;
}

// ---------------- launch: fork preprocessing alongside the GEMM ---------------
extern "C" void kernel_launch(void* const* d_in, const int* in_sizes, int n_in,
                              void* d_out, int out_size) {
    const float* x   = (const float*)d_in[0];
    const void*  src = d_in[1];
    const void*  dst = d_in[2];
    const float* W   = (const float*)d_in[3];
    const float* b   = (const float*)d_in[4];
    const float* W2  = (const float*)d_in[5];
    const float* b2  = (const float*)d_in[6];
    float*       out = (float*)d_out;

    const int nodes = in_sizes[0] / F;     // 100000
    const int nE    = in_sizes[1];         // 1600000
    const int nScanBlocks = (nodes + 255) / 256;

    cudaStream_t sB;
    cudaStreamCreateWithFlags(&sB, cudaStreamNonBlocking);
    cudaEvent_t evFork, evJoin;
    cudaEventCreateWithFlags(&evFork, cudaEventDisableTiming);
    cudaEventCreateWithFlags(&evJoin, cudaEventDisableTiming);

    // main stream: dtype probe (branch B depends on g_is64)
    detect_kernel<<<1, 256>>>((const unsigned int*)src);

    // fork branch B: zero -> degrees -> CSR build -> rsqrt precompute
    cudaEventRecord(evFork, 0);
    cudaStreamWaitEvent(sB, evFork, 0);
    zero_kernel<<<256, 256, 0, sB>>>(nodes);
    deg_kernel<<<(nE + 255) / 256, 256, 0, sB>>>(src, dst, nE);
    rs_kernel<<<(nodes + 255) / 256, 256, 0, sB>>>(nodes);
    scan_a_kernel<<<nScanBlocks, 256, 0, sB>>>(nodes);
    scan_b_kernel<<<1, SCAN_BLOCKS, 0, sB>>>(nScanBlocks);
    scan_c_kernel<<<nScanBlocks, 256, 0, sB>>>(nodes);
    scatter_kernel<<<(nE + 255) / 256, 256, 0, sB>>>(src, dst, nE);
    cudaEventRecord(evJoin, sB);

    // main stream: GEMM overlaps branch B (no dependency on degrees anymore)
    dim3 ggrid((nodes + BM - 1) / BM, F / BN);
    gemm_kernel<<<ggrid, 256>>>(x, W, nodes);

    // join, then aggregate + head
    cudaStreamWaitEvent(0, evJoin, 0);
    int ablocks = (nodes + 7) / 8;
    agg_kernel<<<ablocks, 256>>>(b, nodes);
    head_kernel<<<1, C>>>(W2, b2, out, 1.0f / (float)nodes);

    cudaEventDestroy(evFork);
    cudaEventDestroy(evJoin);
    cudaStreamDestroy(sB);
}

// round 9
// speedup vs baseline: 1.2186x; 1.0886x over previous
#include <cuda_runtime.h>
#include <cstdint>

#define N_NODES 100000
#define N_EDGES 1600000
#define F 256          // IN_FEATS == H_FEATS
#define C 64           // NUM_CLASSES

// ---------------- scratch (static device globals; no allocation) -------------
__device__ int   g_deg_out[N_NODES];
__device__ int   g_deg_in[N_NODES];
__device__ float g_rs_out[N_NODES];             // rsqrt(max(deg_out,1))
__device__ float g_h[(size_t)N_NODES * F];      // x @ W  (unscaled)
__device__ float g_pooled[F];
__device__ int   g_is64;
// CSR-by-dst
__device__ int   g_row_ptr[N_NODES + 1];
__device__ int   g_cursor[N_NODES];
__device__ int   g_edge_src[N_EDGES];
#define SCAN_BLOCKS 1024
__device__ int   g_blocksum[SCAN_BLOCKS];
__device__ int   g_blockoff[SCAN_BLOCKS];

// ---------------- K-1: index dtype probe --------------------------------------
__global__ void detect_kernel(const unsigned int* __restrict__ words) {
    __shared__ int nonzero;
    if (threadIdx.x == 0) nonzero = 0;
    __syncthreads();
    for (int p = threadIdx.x; p < 1024; p += blockDim.x)
        if (words[2 * p + 1] != 0u) atomicOr(&nonzero, 1);
    __syncthreads();
    if (threadIdx.x == 0) g_is64 = (nonzero == 0) ? 1 : 0;
}

__device__ __forceinline__ int load_idx(const void* p, int i, int is64) {
    return is64 ? (int)((const long long*)p)[i] : ((const int*)p)[i];
}

// ---------------- K0: zero scratch -------------------------------------------
__global__ void zero_kernel(int nodes) {
    int tid    = blockIdx.x * blockDim.x + threadIdx.x;
    int stride = gridDim.x * blockDim.x;
    for (int i = tid; i < nodes; i += stride) {
        g_deg_out[i] = 0;
        g_deg_in[i]  = 0;
    }
    if (tid < F) g_pooled[tid] = 0.f;
}

// ---------------- K1: degree counts ------------------------------------------
__global__ void deg_kernel(const void* __restrict__ src,
                           const void* __restrict__ dst, int nE) {
    int i = blockIdx.x * blockDim.x + threadIdx.x;
    int is64 = g_is64;
    if (i < nE) {
        atomicAdd(&g_deg_out[load_idx(src, i, is64)], 1);
        atomicAdd(&g_deg_in[load_idx(dst, i, is64)], 1);
    }
}

__global__ void rs_kernel(int nodes) {
    int i = blockIdx.x * blockDim.x + threadIdx.x;
    if (i < nodes) g_rs_out[i] = rsqrtf((float)max(g_deg_out[i], 1));
}

// ---------------- CSR build: 3-phase block scan of deg_in --------------------
__global__ void scan_a_kernel(int nodes) {
    __shared__ int s[256];
    int i = blockIdx.x * 256 + threadIdx.x;
    s[threadIdx.x] = (i < nodes) ? g_deg_in[i] : 0;
    __syncthreads();
#pragma unroll
    for (int off = 128; off > 0; off >>= 1) {
        if (threadIdx.x < off) s[threadIdx.x] += s[threadIdx.x + off];
        __syncthreads();
    }
    if (threadIdx.x == 0) g_blocksum[blockIdx.x] = s[0];
}

__global__ void scan_b_kernel(int nblocks) {
    __shared__ int s[SCAN_BLOCKS];
    int t = threadIdx.x;
    s[t] = (t < nblocks) ? g_blocksum[t] : 0;
    __syncthreads();
#pragma unroll
    for (int off = 1; off < SCAN_BLOCKS; off <<= 1) {
        int v = (t >= off) ? s[t - off] : 0;
        __syncthreads();
        s[t] += v;
        __syncthreads();
    }
    if (t < nblocks) g_blockoff[t] = (t == 0) ? 0 : s[t - 1];
}

__global__ void scan_c_kernel(int nodes) {
    __shared__ int s[256];
    int i = blockIdx.x * 256 + threadIdx.x;
    int t = threadIdx.x;
    int d = (i < nodes) ? g_deg_in[i] : 0;
    s[t] = d;
    __syncthreads();
#pragma unroll
    for (int off = 1; off < 256; off <<= 1) {
        int v = (t >= off) ? s[t - off] : 0;
        __syncthreads();
        s[t] += v;
        __syncthreads();
    }
    int excl = g_blockoff[blockIdx.x] + s[t] - d;
    if (i < nodes) {
        g_row_ptr[i] = excl;
        g_cursor[i]  = excl;
        if (i == nodes - 1) g_row_ptr[nodes] = excl + d;
    }
}

__global__ void scatter_kernel(const void* __restrict__ src,
                               const void* __restrict__ dst, int nE) {
    int i = blockIdx.x * blockDim.x + threadIdx.x;
    int is64 = g_is64;
    if (i < nE) {
        int d = load_idx(dst, i, is64);
        int pos = atomicAdd(&g_cursor[d], 1);
        g_edge_src[pos] = load_idx(src, i, is64);
    }
}

// ---------------- K2: TF32 tensor-core GEMM  h = x @ W -----------------------
// 128x128 block tile, BK=16 (2 k-steps of 8), 8 warps as 4(m) x 2(n).
// Warp tile 32x64: 2 m16-frags x 8 n8-frags, mma.sync.m16n8k8.tf32.
// Smem holds fragment-PERMUTED tiles so frag loads are conflict-free LDS.64
// (float2 fetches both k-steps at once).
//
// A perm layout: [m16 0..7][reg 0..3][lane 0..31][kstep 0..1]  (uint32)
//   reg = (rowlo>=8) + 2*(cc>=4); lane = (rowlo&7)*4 + (cc&3)
// B perm layout: [n8 0..15][reg 0..1][laneq 0..31][kstep 0..1]
//   reg = (kk>=4); laneq = (kk&3)*8 + (n&7)
#define TBM 128
#define TBN 128
#define TBK 16

__device__ __forceinline__ unsigned f2tf32(float f) {
    unsigned u;
    asm("cvt.rna.tf32.f32 %0, %1;" : "=r"(u) : "f"(f));
    return u;
}

__device__ __forceinline__ void mma_tf32(float c[4], const unsigned a[4], const unsigned b[2]) {
    asm volatile(
        "mma.sync.aligned.m16n8k8.row.col.f32.tf32.tf32.f32 "
        "{%0,%1,%2,%3}, {%4,%5,%6,%7}, {%8,%9}, {%0,%1,%2,%3};"
        : "+f"(c[0]), "+f"(c[1]), "+f"(c[2]), "+f"(c[3])
        : "r"(a[0]), "r"(a[1]), "r"(a[2]), "r"(a[3]), "r"(b[0]), "r"(b[1]));
}

__global__ __launch_bounds__(256, 1) void gemm_tc_kernel(const float* __restrict__ x,
                                                         const float* __restrict__ W,
                                                         int M) {
    __shared__ unsigned As[8][4][32][2];    // 8KB
    __shared__ unsigned Bs[16][2][32][2];   // 8KB

    const int t      = threadIdx.x;
    const int lane   = t & 31;
    const int wid    = t >> 5;
    const int warp_m = wid & 3;          // 0..3 -> m offset *32
    const int warp_n = wid >> 2;         // 0..1 -> n offset *64
    const int bm     = blockIdx.x * TBM;
    const int bn     = blockIdx.y * TBN;

    // gmem->smem mapping (per thread: 2 float4 for A, 2 float4 for B)
    const int aRow  = t >> 2;            // 0..63 (+64)
    const int aKc4  = (t & 3) << 2;      // 0,4,8,12
    const int bK    = t >> 5;            // 0..7 (+8)
    const int bNc4  = (t & 31) << 2;     // 0..124

    float acc[2][8][4];
#pragma unroll
    for (int i = 0; i < 2; i++)
#pragma unroll
        for (int j = 0; j < 8; j++)
#pragma unroll
            for (int r = 0; r < 4; r++) acc[i][j][r] = 0.f;

    const int g = lane >> 2;             // groupID
    const int tg = lane & 3;             // tid in group
    const int laneq = tg * 8 + g;        // B frag load index

    for (int k0 = 0; k0 < F; k0 += TBK) {
        // ---- A tile: rows bm..bm+127, cols k0..k0+15, permuted store ----
        {
            const int kstep = aKc4 >> 3;          // 0 or 1
            const int cch   = (aKc4 & 7) >> 2;    // 0: cc<4, 1: cc>=4
#pragma unroll
            for (int half = 0; half < 2; half++) {
                int r = aRow + half * 64;
                float4 av = make_float4(0.f, 0.f, 0.f, 0.f);
                if (bm + r < M)
                    av = *reinterpret_cast<const float4*>(x + (size_t)(bm + r) * F + k0 + aKc4);
                int m16  = r >> 4;
                int rlo  = r & 15;
                int reg  = ((rlo >= 8) ? 1 : 0) + 2 * cch;
                int lb   = (rlo & 7) * 4;
                As[m16][reg][lb + 0][kstep] = f2tf32(av.x);
                As[m16][reg][lb + 1][kstep] = f2tf32(av.y);
                As[m16][reg][lb + 2][kstep] = f2tf32(av.z);
                As[m16][reg][lb + 3][kstep] = f2tf32(av.w);
            }
        }
        // ---- B tile: rows k0..k0+15, cols bn..bn+127, permuted store ----
        {
#pragma unroll
            for (int half = 0; half < 2; half++) {
                int k = bK + half * 8;
                float4 bv = *reinterpret_cast<const float4*>(W + (size_t)(k0 + k) * F + bn + bNc4);
                int kstep = k >> 3;
                int kk    = k & 7;
                int reg   = (kk >= 4) ? 1 : 0;
                int tgk   = kk & 3;
                int n8    = bNc4 >> 3;
                int gb    = bNc4 & 7;             // 0 or 4
                Bs[n8][reg][tgk * 8 + gb + 0][kstep] = f2tf32(bv.x);
                Bs[n8][reg][tgk * 8 + gb + 1][kstep] = f2tf32(bv.y);
                Bs[n8][reg][tgk * 8 + gb + 2][kstep] = f2tf32(bv.z);
                Bs[n8][reg][tgk * 8 + gb + 3][kstep] = f2tf32(bv.w);
            }
        }
        __syncthreads();

        // ---- fragment loads (both k-steps via LDS.64) ----
        unsigned afr[2][2][4];   // [mi][kstep][reg]
        unsigned bfr[8][2][2];   // [ni][kstep][reg]
#pragma unroll
        for (int mi = 0; mi < 2; mi++) {
            int m16 = warp_m * 2 + mi;
#pragma unroll
            for (int r = 0; r < 4; r++) {
                uint2 v = *reinterpret_cast<const uint2*>(&As[m16][r][lane][0]);
                afr[mi][0][r] = v.x;
                afr[mi][1][r] = v.y;
            }
        }
#pragma unroll
        for (int ni = 0; ni < 8; ni++) {
            int n8 = warp_n * 8 + ni;
#pragma unroll
            for (int r = 0; r < 2; r++) {
                uint2 v = *reinterpret_cast<const uint2*>(&Bs[n8][r][laneq][0]);
                bfr[ni][0][r] = v.x;
                bfr[ni][1][r] = v.y;
            }
        }

        // ---- 2 k-steps x 2 m x 8 n mma ----
#pragma unroll
        for (int ks = 0; ks < 2; ks++)
#pragma unroll
            for (int mi = 0; mi < 2; mi++)
#pragma unroll
                for (int ni = 0; ni < 8; ni++)
                    mma_tf32(acc[mi][ni], afr[mi][ks], bfr[ni][ks]);

        __syncthreads();
    }

    // ---- epilogue: C frag (g, 2t),(g,2t+1),(g+8,2t),(g+8,2t+1) ----
#pragma unroll
    for (int mi = 0; mi < 2; mi++) {
        int rowA = bm + warp_m * 32 + mi * 16 + g;
        int rowB = rowA + 8;
#pragma unroll
        for (int ni = 0; ni < 8; ni++) {
            int col = bn + warp_n * 64 + ni * 8 + tg * 2;
            if (rowA < M)
                *reinterpret_cast<float2*>(g_h + (size_t)rowA * F + col) =
                    make_float2(acc[mi][ni][0], acc[mi][ni][1]);
            if (rowB < M)
                *reinterpret_cast<float2*>(g_h + (size_t)rowB * F + col) =
                    make_float2(acc[mi][ni][2], acc[mi][ni][3]);
        }
    }
}

// ---------------- K3: CSR aggregate + epilogue + pool -------------------------
__global__ __launch_bounds__(256) void agg_kernel(const float* __restrict__ b,
                                                  int nodes) {
    __shared__ float pooled_s[F];
    if (threadIdx.x < F) pooled_s[threadIdx.x] = 0.f;
    __syncthreads();

    int warp = (blockIdx.x * blockDim.x + threadIdx.x) >> 5;
    int lane = threadIdx.x & 31;

    if (warp < nodes) {
        int begin = g_row_ptr[warp];
        int end   = g_row_ptr[warp + 1];

        float4 a0 = make_float4(0.f, 0.f, 0.f, 0.f);
        float4 a1 = make_float4(0.f, 0.f, 0.f, 0.f);

        int e = begin;
        for (; e + 1 < end; e += 2) {
            int s0 = g_edge_src[e];
            int s1 = g_edge_src[e + 1];
            float w0 = g_rs_out[s0];
            float w1 = g_rs_out[s1];
            const float4* r0 = reinterpret_cast<const float4*>(g_h + (size_t)s0 * F);
            const float4* r1 = reinterpret_cast<const float4*>(g_h + (size_t)s1 * F);
            float4 v00 = r0[lane], v01 = r0[lane + 32];
            float4 v10 = r1[lane], v11 = r1[lane + 32];
            a0.x = fmaf(v00.x, w0, a0.x); a0.y = fmaf(v00.y, w0, a0.y);
            a0.z = fmaf(v00.z, w0, a0.z); a0.w = fmaf(v00.w, w0, a0.w);
            a1.x = fmaf(v01.x, w0, a1.x); a1.y = fmaf(v01.y, w0, a1.y);
            a1.z = fmaf(v01.z, w0, a1.z); a1.w = fmaf(v01.w, w0, a1.w);
            a0.x = fmaf(v10.x, w1, a0.x); a0.y = fmaf(v10.y, w1, a0.y);
            a0.z = fmaf(v10.z, w1, a0.z); a0.w = fmaf(v10.w, w1, a0.w);
            a1.x = fmaf(v11.x, w1, a1.x); a1.y = fmaf(v11.y, w1, a1.y);
            a1.z = fmaf(v11.z, w1, a1.z); a1.w = fmaf(v11.w, w1, a1.w);
        }
        if (e < end) {
            int s0 = g_edge_src[e];
            float w0 = g_rs_out[s0];
            const float4* r0 = reinterpret_cast<const float4*>(g_h + (size_t)s0 * F);
            float4 v00 = r0[lane], v01 = r0[lane + 32];
            a0.x = fmaf(v00.x, w0, a0.x); a0.y = fmaf(v00.y, w0, a0.y);
            a0.z = fmaf(v00.z, w0, a0.z); a0.w = fmaf(v00.w, w0, a0.w);
            a1.x = fmaf(v01.x, w0, a1.x); a1.y = fmaf(v01.y, w0, a1.y);
            a1.z = fmaf(v01.z, w0, a1.z); a1.w = fmaf(v01.w, w0, a1.w);
        }

        float rs = rsqrtf((float)max(end - begin, 1));
        const float4* b4 = reinterpret_cast<const float4*>(b);
        float4 b0 = b4[lane], b1 = b4[lane + 32];

        float4 o0, o1;
        o0.x = fmaxf(fmaf(a0.x, rs, b0.x), 0.f);
        o0.y = fmaxf(fmaf(a0.y, rs, b0.y), 0.f);
        o0.z = fmaxf(fmaf(a0.z, rs, b0.z), 0.f);
        o0.w = fmaxf(fmaf(a0.w, rs, b0.w), 0.f);
        o1.x = fmaxf(fmaf(a1.x, rs, b1.x), 0.f);
        o1.y = fmaxf(fmaf(a1.y, rs, b1.y), 0.f);
        o1.z = fmaxf(fmaf(a1.z, rs, b1.z), 0.f);
        o1.w = fmaxf(fmaf(a1.w, rs, b1.w), 0.f);

        int f0 = lane << 2;
        atomicAdd(&pooled_s[f0 + 0], o0.x);
        atomicAdd(&pooled_s[f0 + 1], o0.y);
        atomicAdd(&pooled_s[f0 + 2], o0.z);
        atomicAdd(&pooled_s[f0 + 3], o0.w);
        int f1 = (lane + 32) << 2;
        atomicAdd(&pooled_s[f1 + 0], o1.x);
        atomicAdd(&pooled_s[f1 + 1], o1.y);
        atomicAdd(&pooled_s[f1 + 2], o1.z);
        atomicAdd(&pooled_s[f1 + 3], o1.w);
    }

    __syncthreads();
    if (threadIdx.x < F) atomicAdd(&g_pooled[threadIdx.x], pooled_s[threadIdx.x]);
}

// ---------------- K5: head  softmax(pooled/N @ W2 + b2) ----------------------
__global__ __launch_bounds__(64) void head_kernel(const float* __restrict__ W2,
                                                  const float* __restrict__ b2,
                                                  float* __restrict__ out, float invN) {
    __shared__ float pooled_s[F];
    __shared__ float sm[C];
    int t = threadIdx.x;
    for (int j = t; j < F; j += C) pooled_s[j] = g_pooled[j] * invN;
    __syncthreads();

    float acc = b2[t];
#pragma unroll 8
    for (int j = 0; j < F; j++) acc = fmaf(pooled_s[j], W2[(size_t)j * C + t], acc);

    sm[t] = acc;
    __syncthreads();
    float m = sm[0];
#pragma unroll
    for (int j = 1; j < C; j++) m = fmaxf(m, sm[j]);
    __syncthreads();
    float e = expf(acc - m);
    sm[t] = e;
    __syncthreads();
    float ssum = 0.f;
#pragma unroll
    for (int j = 0; j < C; j++) ssum += sm[j];
    out[t] = e / ssum;
}

// ---------------- launch -------------------------------------------------------
extern "C" void kernel_launch(void* const* d_in, const int* in_sizes, int n_in,
                              void* d_out, int out_size) {
    const float* x   = (const float*)d_in[0];
    const void*  src = d_in[1];
    const void*  dst = d_in[2];
    const float* W   = (const float*)d_in[3];
    const float* b   = (const float*)d_in[4];
    const float* W2  = (const float*)d_in[5];
    const float* b2  = (const float*)d_in[6];
    float*       out = (float*)d_out;

    const int nodes = in_sizes[0] / F;     // 100000
    const int nE    = in_sizes[1];         // 1600000
    const int nScanBlocks = (nodes + 255) / 256;

    cudaStream_t sB;
    cudaStreamCreateWithFlags(&sB, cudaStreamNonBlocking);
    cudaEvent_t evFork, evJoin;
    cudaEventCreateWithFlags(&evFork, cudaEventDisableTiming);
    cudaEventCreateWithFlags(&evJoin, cudaEventDisableTiming);

    detect_kernel<<<1, 256>>>((const unsigned int*)src);

    // branch B: zero -> degrees -> rsqrt -> CSR build
    cudaEventRecord(evFork, 0);
    cudaStreamWaitEvent(sB, evFork, 0);
    zero_kernel<<<256, 256, 0, sB>>>(nodes);
    deg_kernel<<<(nE + 255) / 256, 256, 0, sB>>>(src, dst, nE);
    rs_kernel<<<(nodes + 255) / 256, 256, 0, sB>>>(nodes);
    scan_a_kernel<<<nScanBlocks, 256, 0, sB>>>(nodes);
    scan_b_kernel<<<1, SCAN_BLOCKS, 0, sB>>>(nScanBlocks);
    scan_c_kernel<<<nScanBlocks, 256, 0, sB>>>(nodes);
    scatter_kernel<<<(nE + 255) / 256, 256, 0, sB>>>(src, dst, nE);
    cudaEventRecord(evJoin, sB);

    // main: TF32 tensor-core GEMM
    dim3 ggrid((nodes + TBM - 1) / TBM, F / TBN);
    gemm_tc_kernel<<<ggrid, 256>>>(x, W, nodes);

    cudaStreamWaitEvent(0, evJoin, 0);
    int ablocks = (nodes + 7) / 8;
    agg_kernel<<<ablocks, 256>>>(b, nodes);
    head_kernel<<<1, C>>>(W2, b2, out, 1.0f / (float)nodes);

    cudaEventDestroy(evFork);
    cudaEventDestroy(evJoin);
    cudaStreamDestroy(sB);
}

// round 10
// speedup vs baseline: 1.2190x; 1.0004x over previous
#include <cuda_runtime.h>
#include <cstdint>

#define N_NODES 100000
#define N_EDGES 1600000
#define F 256          // IN_FEATS == H_FEATS
#define C 64           // NUM_CLASSES

// ---------------- scratch (static device globals; no allocation) -------------
__device__ int   g_deg_out[N_NODES];
__device__ int   g_deg_in[N_NODES];
__device__ float g_rs_out[N_NODES];             // rsqrt(max(deg_out,1))
__device__ float g_h[(size_t)N_NODES * F];      // x @ W  (unscaled)
__device__ float g_pooled[F];
__device__ int   g_is64;
// CSR-by-dst
__device__ int   g_row_ptr[N_NODES + 1];
__device__ int   g_cursor[N_NODES];
__device__ int   g_edge_src[N_EDGES];
#define SCAN_BLOCKS 1024
__device__ int   g_blocksum[SCAN_BLOCKS];
__device__ int   g_blockoff[SCAN_BLOCKS];

// ---------------- K-1: index dtype probe --------------------------------------
__global__ void detect_kernel(const unsigned int* __restrict__ words) {
    __shared__ int nonzero;
    if (threadIdx.x == 0) nonzero = 0;
    __syncthreads();
    for (int p = threadIdx.x; p < 1024; p += blockDim.x)
        if (words[2 * p + 1] != 0u) atomicOr(&nonzero, 1);
    __syncthreads();
    if (threadIdx.x == 0) g_is64 = (nonzero == 0) ? 1 : 0;
}

__device__ __forceinline__ int load_idx(const void* p, int i, int is64) {
    return is64 ? (int)((const long long*)p)[i] : ((const int*)p)[i];
}

// ---------------- K0: zero scratch -------------------------------------------
__global__ void zero_kernel(int nodes) {
    int tid    = blockIdx.x * blockDim.x + threadIdx.x;
    int stride = gridDim.x * blockDim.x;
    for (int i = tid; i < nodes; i += stride) {
        g_deg_out[i] = 0;
        g_deg_in[i]  = 0;
    }
    if (tid < F) g_pooled[tid] = 0.f;
}

// ---------------- K1: degree counts ------------------------------------------
__global__ void deg_kernel(const void* __restrict__ src,
                           const void* __restrict__ dst, int nE) {
    int i = blockIdx.x * blockDim.x + threadIdx.x;
    int is64 = g_is64;
    if (i < nE) {
        atomicAdd(&g_deg_out[load_idx(src, i, is64)], 1);
        atomicAdd(&g_deg_in[load_idx(dst, i, is64)], 1);
    }
}

__global__ void rs_kernel(int nodes) {
    int i = blockIdx.x * blockDim.x + threadIdx.x;
    if (i < nodes) g_rs_out[i] = rsqrtf((float)max(g_deg_out[i], 1));
}

// ---------------- CSR build: 3-phase block scan of deg_in --------------------
__global__ void scan_a_kernel(int nodes) {
    __shared__ int s[256];
    int i = blockIdx.x * 256 + threadIdx.x;
    s[threadIdx.x] = (i < nodes) ? g_deg_in[i] : 0;
    __syncthreads();
#pragma unroll
    for (int off = 128; off > 0; off >>= 1) {
        if (threadIdx.x < off) s[threadIdx.x] += s[threadIdx.x + off];
        __syncthreads();
    }
    if (threadIdx.x == 0) g_blocksum[blockIdx.x] = s[0];
}

__global__ void scan_b_kernel(int nblocks) {
    __shared__ int s[SCAN_BLOCKS];
    int t = threadIdx.x;
    s[t] = (t < nblocks) ? g_blocksum[t] : 0;
    __syncthreads();
#pragma unroll
    for (int off = 1; off < SCAN_BLOCKS; off <<= 1) {
        int v = (t >= off) ? s[t - off] : 0;
        __syncthreads();
        s[t] += v;
        __syncthreads();
    }
    if (t < nblocks) g_blockoff[t] = (t == 0) ? 0 : s[t - 1];
}

__global__ void scan_c_kernel(int nodes) {
    __shared__ int s[256];
    int i = blockIdx.x * 256 + threadIdx.x;
    int t = threadIdx.x;
    int d = (i < nodes) ? g_deg_in[i] : 0;
    s[t] = d;
    __syncthreads();
#pragma unroll
    for (int off = 1; off < 256; off <<= 1) {
        int v = (t >= off) ? s[t - off] : 0;
        __syncthreads();
        s[t] += v;
        __syncthreads();
    }
    int excl = g_blockoff[blockIdx.x] + s[t] - d;
    if (i < nodes) {
        g_row_ptr[i] = excl;
        g_cursor[i]  = excl;
        if (i == nodes - 1) g_row_ptr[nodes] = excl + d;
    }
}

__global__ void scatter_kernel(const void* __restrict__ src,
                               const void* __restrict__ dst, int nE) {
    int i = blockIdx.x * blockDim.x + threadIdx.x;
    int is64 = g_is64;
    if (i < nE) {
        int d = load_idx(dst, i, is64);
        int pos = atomicAdd(&g_cursor[d], 1);
        g_edge_src[pos] = load_idx(src, i, is64);
    }
}

// ---------------- K2: TF32 tensor-core GEMM  h = x @ W -----------------------
// 128x128 block tile, BK=16 (2 k-steps of 8), 8 warps as 4(m) x 2(n).
// Warp tile 32x64: 2 m16-frags x 8 n8-frags, mma.sync.m16n8k8.tf32.
// Smem holds fragment-PERMUTED tiles so frag loads are conflict-free LDS.64
// (float2 fetches both k-steps at once).
//
// A perm layout: [m16 0..7][reg 0..3][lane 0..31][kstep 0..1]  (uint32)
//   reg = (rowlo>=8) + 2*(cc>=4); lane = (rowlo&7)*4 + (cc&3)
// B perm layout: [n8 0..15][reg 0..1][laneq 0..31][kstep 0..1]
//   reg = (kk>=4); laneq = (kk&3)*8 + (n&7)
#define TBM 128
#define TBN 128
#define TBK 16

__device__ __forceinline__ unsigned f2tf32(float f) {
    unsigned u;
    asm("cvt.rna.tf32.f32 %0, %1;" : "=r"(u) : "f"(f));
    return u;
}

__device__ __forceinline__ void mma_tf32(float c[4], const unsigned a[4], const unsigned b[2]) {
    asm volatile(
        "mma.sync.aligned.m16n8k8.row.col.f32.tf32.tf32.f32 "
        "{%0,%1,%2,%3}, {%4,%5,%6,%7}, {%8,%9}, {%0,%1,%2,%3};"
        : "+f"(c[0]), "+f"(c[1]), "+f"(c[2]), "+f"(c[3])
        : "r"(a[0]), "r"(a[1]), "r"(a[2]), "r"(a[3]), "r"(b[0]), "r"(b[1]));
}

__global__ __launch_bounds__(256, 1) void gemm_tc_kernel(const float* __restrict__ x,
                                                         const float* __restrict__ W,
                                                         int M) {
    __shared__ unsigned As[8][4][32][2];    // 8KB
    __shared__ unsigned Bs[16][2][32][2];   // 8KB

    const int t      = threadIdx.x;
    const int lane   = t & 31;
    const int wid    = t >> 5;
    const int warp_m = wid & 3;          // 0..3 -> m offset *32
    const int warp_n = wid >> 2;         // 0..1 -> n offset *64
    const int bm     = blockIdx.x * TBM;
    const int bn     = blockIdx.y * TBN;

    // gmem->smem mapping (per thread: 2 float4 for A, 2 float4 for B)
    const int aRow  = t >> 2;            // 0..63 (+64)
    const int aKc4  = (t & 3) << 2;      // 0,4,8,12
    const int bK    = t >> 5;            // 0..7 (+8)
    const int bNc4  = (t & 31) << 2;     // 0..124

    float acc[2][8][4];
#pragma unroll
    for (int i = 0; i < 2; i++)
#pragma unroll
        for (int j = 0; j < 8; j++)
#pragma unroll
            for (int r = 0; r < 4; r++) acc[i][j][r] = 0.f;

    const int g = lane >> 2;             // groupID
    const int tg = lane & 3;             // tid in group
    const int laneq = tg * 8 + g;        // B frag load index

    for (int k0 = 0; k0 < F; k0 += TBK) {
        // ---- A tile: rows bm..bm+127, cols k0..k0+15, permuted store ----
        {
            const int kstep = aKc4 >> 3;          // 0 or 1
            const int cch   = (aKc4 & 7) >> 2;    // 0: cc<4, 1: cc>=4
#pragma unroll
            for (int half = 0; half < 2; half++) {
                int r = aRow + half * 64;
                float4 av = make_float4(0.f, 0.f, 0.f, 0.f);
                if (bm + r < M)
                    av = *reinterpret_cast<const float4*>(x + (size_t)(bm + r) * F + k0 + aKc4);
                int m16  = r >> 4;
                int rlo  = r & 15;
                int reg  = ((rlo >= 8) ? 1 : 0) + 2 * cch;
                int lb   = (rlo & 7) * 4;
                As[m16][reg][lb + 0][kstep] = f2tf32(av.x);
                As[m16][reg][lb + 1][kstep] = f2tf32(av.y);
                As[m16][reg][lb + 2][kstep] = f2tf32(av.z);
                As[m16][reg][lb + 3][kstep] = f2tf32(av.w);
            }
        }
        // ---- B tile: rows k0..k0+15, cols bn..bn+127, permuted store ----
        {
#pragma unroll
            for (int half = 0; half < 2; half++) {
                int k = bK + half * 8;
                float4 bv = *reinterpret_cast<const float4*>(W + (size_t)(k0 + k) * F + bn + bNc4);
                int kstep = k >> 3;
                int kk    = k & 7;
                int reg   = (kk >= 4) ? 1 : 0;
                int tgk   = kk & 3;
                int n8    = bNc4 >> 3;
                int gb    = bNc4 & 7;             // 0 or 4
                Bs[n8][reg][tgk * 8 + gb + 0][kstep] = f2tf32(bv.x);
                Bs[n8][reg][tgk * 8 + gb + 1][kstep] = f2tf32(bv.y);
                Bs[n8][reg][tgk * 8 + gb + 2][kstep] = f2tf32(bv.z);
                Bs[n8][reg][tgk * 8 + gb + 3][kstep] = f2tf32(bv.w);
            }
        }
        __syncthreads();

        // ---- fragment loads (both k-steps via LDS.64) ----
        unsigned afr[2][2][4];   // [mi][kstep][reg]
        unsigned bfr[8][2][2];   // [ni][kstep][reg]
#pragma unroll
        for (int mi = 0; mi < 2; mi++) {
            int m16 = warp_m * 2 + mi;
#pragma unroll
            for (int r = 0; r < 4; r++) {
                uint2 v = *reinterpret_cast<const uint2*>(&As[m16][r][lane][0]);
                afr[mi][0][r] = v.x;
                afr[mi][1][r] = v.y;
            }
        }
#pragma unroll
        for (int ni = 0; ni < 8; ni++) {
            int n8 = warp_n * 8 + ni;
#pragma unroll
            for (int r = 0; r < 2; r++) {
                uint2 v = *reinterpret_cast<const uint2*>(&Bs[n8][r][laneq][0]);
                bfr[ni][0][r] = v.x;
                bfr[ni][1][r] = v.y;
            }
        }

        // ---- 2 k-steps x 2 m x 8 n mma ----
#pragma unroll
        for (int ks = 0; ks < 2; ks++)
#pragma unroll
            for (int mi = 0; mi < 2; mi++)
#pragma unroll
                for (int ni = 0; ni < 8; ni++)
                    mma_tf32(acc[mi][ni], afr[mi][ks], bfr[ni][ks]);

        __syncthreads();
    }

    // ---- epilogue: C frag (g, 2t),(g,2t+1),(g+8,2t),(g+8,2t+1) ----
#pragma unroll
    for (int mi = 0; mi < 2; mi++) {
        int rowA = bm + warp_m * 32 + mi * 16 + g;
        int rowB = rowA + 8;
#pragma unroll
        for (int ni = 0; ni < 8; ni++) {
            int col = bn + warp_n * 64 + ni * 8 + tg * 2;
            if (rowA < M)
                *reinterpret_cast<float2*>(g_h + (size_t)rowA * F + col) =
                    make_float2(acc[mi][ni][0], acc[mi][ni][1]);
            if (rowB < M)
                *reinterpret_cast<float2*>(g_h + (size_t)rowB * F + col) =
                    make_float2(acc[mi][ni][2], acc[mi][ni][3]);
        }
    }
}

// ---------------- K3: CSR aggregate + epilogue + pool -------------------------
__global__ __launch_bounds__(256) void agg_kernel(const float* __restrict__ b,
                                                  int nodes) {
    __shared__ float pooled_s[F];
    if (threadIdx.x < F) pooled_s[threadIdx.x] = 0.f;
    __syncthreads();

    int warp = (blockIdx.x * blockDim.x + threadIdx.x) >> 5;
    int lane = threadIdx.x & 31;

    if (warp < nodes) {
        int begin = g_row_ptr[warp];
        int end   = g_row_ptr[warp + 1];

        float4 a0 = make_float4(0.f, 0.f, 0.f, 0.f);
        float4 a1 = make_float4(0.f, 0.f, 0.f, 0.f);

        int e = begin;
        for (; e + 1 < end; e += 2) {
            int s0 = g_edge_src[e];
            int s1 = g_edge_src[e + 1];
            float w0 = g_rs_out[s0];
            float w1 = g_rs_out[s1];
            const float4* r0 = reinterpret_cast<const float4*>(g_h + (size_t)s0 * F);
            const float4* r1 = reinterpret_cast<const float4*>(g_h + (size_t)s1 * F);
            float4 v00 = r0[lane], v01 = r0[lane + 32];
            float4 v10 = r1[lane], v11 = r1[lane + 32];
            a0.x = fmaf(v00.x, w0, a0.x); a0.y = fmaf(v00.y, w0, a0.y);
            a0.z = fmaf(v00.z, w0, a0.z); a0.w = fmaf(v00.w, w0, a0.w);
            a1.x = fmaf(v01.x, w0, a1.x); a1.y = fmaf(v01.y, w0, a1.y);
            a1.z = fmaf(v01.z, w0, a1.z); a1.w = fmaf(v01.w, w0, a1.w);
            a0.x = fmaf(v10.x, w1, a0.x); a0.y = fmaf(v10.y, w1, a0.y);
            a0.z = fmaf(v10.z, w1, a0.z); a0.w = fmaf(v10.w, w1, a0.w);
            a1.x = fmaf(v11.x, w1, a1.x); a1.y = fmaf(v11.y, w1, a1.y);
            a1.z = fmaf(v11.z, w1, a1.z); a1.w = fmaf(v11.w, w1, a1.w);
        }
        if (e < end) {
            int s0 = g_edge_src[e];
            float w0 = g_rs_out[s0];
            const float4* r0 = reinterpret_cast<const float4*>(g_h + (size_t)s0 * F);
            float4 v00 = r0[lane], v01 = r0[lane + 32];
            a0.x = fmaf(v00.x, w0, a0.x); a0.y = fmaf(v00.y, w0, a0.y);
            a0.z = fmaf(v00.z, w0, a0.z); a0.w = fmaf(v00.w, w0, a0.w);
            a1.x = fmaf(v01.x, w0, a1.x); a1.y = fmaf(v01.y, w0, a1.y);
            a1.z = fmaf(v01.z, w0, a1.z); a1.w = fmaf(v01.w, w0, a1.w);
        }

        float rs = rsqrtf((float)max(end - begin, 1));
        const float4* b4 = reinterpret_cast<const float4*>(b);
        float4 b0 = b4[lane], b1 = b4[lane + 32];

        float4 o0, o1;
        o0.x = fmaxf(fmaf(a0.x, rs, b0.x), 0.f);
        o0.y = fmaxf(fmaf(a0.y, rs, b0.y), 0.f);
        o0.z = fmaxf(fmaf(a0.z, rs, b0.z), 0.f);
        o0.w = fmaxf(fmaf(a0.w, rs, b0.w), 0.f);
        o1.x = fmaxf(fmaf(a1.x, rs, b1.x), 0.f);
        o1.y = fmaxf(fmaf(a1.y, rs, b1.y), 0.f);
        o1.z = fmaxf(fmaf(a1.z, rs, b1.z), 0.f);
        o1.w = fmaxf(fmaf(a1.w, rs, b1.w), 0.f);

        int f0 = lane << 2;
        atomicAdd(&pooled_s[f0 + 0], o0.x);
        atomicAdd(&pooled_s[f0 + 1], o0.y);
        atomicAdd(&pooled_s[f0 + 2], o0.z);
        atomicAdd(&pooled_s[f0 + 3], o0.w);
        int f1 = (lane + 32) << 2;
        atomicAdd(&pooled_s[f1 + 0], o1.x);
        atomicAdd(&pooled_s[f1 + 1], o1.y);
        atomicAdd(&pooled_s[f1 + 2], o1.z);
        atomicAdd(&pooled_s[f1 + 3], o1.w);
    }

    __syncthreads();
    if (threadIdx.x < F) atomicAdd(&g_pooled[threadIdx.x], pooled_s[threadIdx.x]);
}

// ---------------- K5: head  softmax(pooled/N @ W2 + b2) ----------------------
__global__ __launch_bounds__(64) void head_kernel(const float* __restrict__ W2,
                                                  const float* __restrict__ b2,
                                                  float* __restrict__ out, float invN) {
    __shared__ float pooled_s[F];
    __shared__ float sm[C];
    int t = threadIdx.x;
    for (int j = t; j < F; j += C) pooled_s[j] = g_pooled[j] * invN;
    __syncthreads();

    float acc = b2[t];
#pragma unroll 8
    for (int j = 0; j < F; j++) acc = fmaf(pooled_s[j], W2[(size_t)j * C + t], acc);

    sm[t] = acc;
    __syncthreads();
    float m = sm[0];
#pragma unroll
    for (int j = 1; j < C; j++) m = fmaxf(m, sm[j]);
    __syncthreads();
    float e = expf(acc - m);
    sm[t] = e;
    __syncthreads();
    float ssum = 0.f;
#pragma unroll
    for (int j = 0; j < C; j++) ssum += sm[j];
    out[t] = e / ssum;
}

// ---------------- launch -------------------------------------------------------
extern "C" void kernel_launch(void* const* d_in, const int* in_sizes, int n_in,
                              void* d_out, int out_size) {
    const float* x   = (const float*)d_in[0];
    const void*  src = d_in[1];
    const void*  dst = d_in[2];
    const float* W   = (const float*)d_in[3];
    const float* b   = (const float*)d_in[4];
    const float* W2  = (const float*)d_in[5];
    const float* b2  = (const float*)d_in[6];
    float*       out = (float*)d_out;

    const int nodes = in_sizes[0] / F;     // 100000
    const int nE    = in_sizes[1];         // 1600000
    const int nScanBlocks = (nodes + 255) / 256;

    cudaStream_t sB;
    cudaStreamCreateWithFlags(&sB, cudaStreamNonBlocking);
    cudaEvent_t evFork, evJoin;
    cudaEventCreateWithFlags(&evFork, cudaEventDisableTiming);
    cudaEventCreateWithFlags(&evJoin, cudaEventDisableTiming);

    detect_kernel<<<1, 256>>>((const unsigned int*)src);

    // branch B: zero -> degrees -> rsqrt -> CSR build
    cudaEventRecord(evFork, 0);
    cudaStreamWaitEvent(sB, evFork, 0);
    zero_kernel<<<256, 256, 0, sB>>>(nodes);
    deg_kernel<<<(nE + 255) / 256, 256, 0, sB>>>(src, dst, nE);
    rs_kernel<<<(nodes + 255) / 256, 256, 0, sB>>>(nodes);
    scan_a_kernel<<<nScanBlocks, 256, 0, sB>>>(nodes);
    scan_b_kernel<<<1, SCAN_BLOCKS, 0, sB>>>(nScanBlocks);
    scan_c_kernel<<<nScanBlocks, 256, 0, sB>>>(nodes);
    scatter_kernel<<<(nE + 255) / 256, 256, 0, sB>>>(src, dst, nE);
    cudaEventRecord(evJoin, sB);

    // main: TF32 tensor-core GEMM
    dim3 ggrid((nodes + TBM - 1) / TBM, F / TBN);
    gemm_tc_kernel<<<ggrid, 256>>>(x, W, nodes);

    cudaStreamWaitEvent(0, evJoin, 0);
    int ablocks = (nodes + 7) / 8;
    agg_kernel<<<ablocks, 256>>>(b, nodes);
    head_kernel<<<1, C>>>(W2, b2, out, 1.0f / (float)nodes);

    cudaEventDestroy(evFork);
    cudaEventDestroy(evJoin);
    cudaStreamDestroy(sB);
}